// round 12
// baseline (speedup 1.0000x reference)
#include <cuda_runtime.h>
#include <cstdint>

// ---------------- problem constants ----------------
#define STEPS 4096
#define DATA  8192
#define EMBD  1024
#define HDIM  128
#define ODIM  12
#define NCTA  8
#define TPB   256

// ---------------- device scratch (no allocations allowed) ----------------
__device__ float g_Mt[(size_t)DATA * HDIM];     // fused weight Mt[d][i]  (4 MB)
__device__ float g_pre[(size_t)STEPS * HDIM];   // pre_i2h[t][i] + c_fused (2 MB)
__device__ float g_cf[HDIM];                    // fused bias

__device__ __forceinline__ float tanha(float x) {
    float y; asm("tanh.approx.f32 %0, %1;" : "=f"(y) : "f"(x)); return y;
}
__device__ __forceinline__ float sigm(float x) { return 0.5f + 0.5f * tanha(0.5f * x); }

#define CLUSTER_SYNC() do { \
  asm volatile("barrier.cluster.arrive.aligned;" ::: "memory"); \
  asm volatile("barrier.cluster.wait.aligned;"   ::: "memory"); } while (0)

// NOTE: parameter names must not collide with float4 member tokens x/y/z/w
#define FMA4(W_, X_) do { a0 = fmaf((W_).x,(X_).x,a0); a1 = fmaf((W_).y,(X_).y,a1); \
                          a2 = fmaf((W_).z,(X_).z,a2); a3 = fmaf((W_).w,(X_).w,a3); } while (0)

// =====================================================================
// K0: c_fused[i] = b_i2h[i] + sum_e b_s2i[e] * W_i2h[i][e]
// =====================================================================
__global__ void k_cf(const float* __restrict__ b_s2i,
                     const float* __restrict__ Wi2h,
                     const float* __restrict__ b_i2h) {
    int i = threadIdx.x;  // 128 threads
    const float4* b4 = (const float4*)b_s2i;
    const float4* w4 = (const float4*)(Wi2h + (size_t)i * 1152);
    float a0 = 0, a1 = 0, a2 = 0, a3 = 0;
    for (int k = 0; k < EMBD / 4; k++) { float4 bv = b4[k], wv = w4[k]; FMA4(wv, bv); }
    g_cf[i] = b_i2h[i] + ((a0 + a1) + (a2 + a3));
}

// =====================================================================
// K1: Mt[d][i] = sum_e Ws2i[e][d] * Wi2h[i][e]     grid(32,8), 256 thr
// =====================================================================
__global__ void __launch_bounds__(256) k_mt(const float* __restrict__ Ws2i,
                                            const float* __restrict__ Wi2h) {
    __shared__ float we[16][128];
    int d  = blockIdx.x * 256 + threadIdx.x;
    int i0 = blockIdx.y * 16;
    float acc[16];
#pragma unroll
    for (int ii = 0; ii < 16; ii++) acc[ii] = 0.f;
    for (int e0 = 0; e0 < EMBD; e0 += 128) {
#pragma unroll
        for (int k = 0; k < 8; k++) {
            int idx = k * 256 + threadIdx.x;
            int ii = idx >> 7, ee = idx & 127;
            we[ii][ee] = Wi2h[(size_t)(i0 + ii) * 1152 + e0 + ee];
        }
        __syncthreads();
        for (int ee = 0; ee < 128; ee++) {
            float ws = Ws2i[(size_t)(e0 + ee) * DATA + d];
#pragma unroll
            for (int ii = 0; ii < 16; ii++) acc[ii] = fmaf(we[ii][ee], ws, acc[ii]);
        }
        __syncthreads();
    }
#pragma unroll
    for (int ii = 0; ii < 16; ii++) g_Mt[(size_t)d * HDIM + i0 + ii] = acc[ii];
}

// =====================================================================
// K2: pre[t][i] = c_fused[i] + sum_d inputs[t][d] * Mt[d][i]
// =====================================================================
__global__ void __launch_bounds__(256) k_pre(const float* __restrict__ inputs) {
    __shared__ float xin[16 * 64];
    __shared__ float wm[64 * 128];
    int t0   = blockIdx.x * 16;
    int i    = threadIdx.x & 127;
    int trow = threadIdx.x >> 7;  // 0..1
    float acc[8];
#pragma unroll
    for (int k = 0; k < 8; k++) acc[k] = 0.f;
    for (int d0 = 0; d0 < DATA; d0 += 64) {
        {
            int idx = threadIdx.x * 4;
            int tt = idx >> 6, dd = idx & 63;
            *(float4*)&xin[idx] = *(const float4*)&inputs[(size_t)(t0 + tt) * DATA + d0 + dd];
        }
#pragma unroll
        for (int k = 0; k < 8; k++) {
            int x4 = (k * 256 + threadIdx.x) * 4;
            *(float4*)&wm[x4] = *(const float4*)&g_Mt[(size_t)d0 * HDIM + x4];
        }
        __syncthreads();
        for (int dd = 0; dd < 64; dd++) {
            float m = wm[dd * 128 + i];
#pragma unroll
            for (int tt = 0; tt < 8; tt++)
                acc[tt] = fmaf(xin[(trow + tt * 2) * 64 + dd], m, acc[tt]);
        }
        __syncthreads();
    }
    float cf = g_cf[i];
#pragma unroll
    for (int tt = 0; tt < 8; tt++)
        g_pre[(size_t)(t0 + trow + tt * 2) * HDIM + i] = acc[tt] + cf;
}

// =====================================================================
// K3: the sequential scan — 8-CTA cluster, 256 thr/CTA, st.async p2p sync
//
// LSTM map: tid = j*16 + g*4 + cs.  j=tid>>4 (h-index), g=(tid>>2)&3 (gate),
//   cs=tid&3 (32-col slice). Row R = g*128 + rank*16 + j.
// Weight layout: lw[(slot*256 + tid)*4 + c], col = cs*32 + k*4 + c.
//   l1w/l2w: slots 0..7 = ih, 8..15 = hh. l0w: slots 0..2 = ih (12-dim,
//   cs==0 only, rest zero), 3..10 = hh.
// D: r=tid>>4, sub=tid&15, 8 cols each.  E/F: row=tid>>1, half=tid&1,
//   64 cols in regs.  G: tid<192, r=tid>>4, sub=tid&15, 8 cols in regs.
// =====================================================================
#define OFF_L0W   0         /* 11264 */
#define OFF_L1W   11264     /* 16384 */
#define OFF_L2W   27648     /* 16384 */
#define OFF_WD    44032     /* 2048  */
#define OFF_BHH   46080     /* 128   */
#define OFF_BH2O  46208     /* 16    */
#define OFF_H0    46224     /* 256   */
#define OFF_H1    46480     /* 256   */
#define OFF_H2    46736     /* 256   */
#define OFF_HD    46992     /* 128   */
#define OFF_HE    47120     /* 128   */
#define OFF_HF    47248     /* 128   */
#define OFF_OBUF  47376     /* 16    */
#define OFF_MBAR  47392     /* 4 mbarriers = 8 floats (8B aligned) */
#define SMEM_FLOATS 47400
#define SMEM_BYTES  (SMEM_FLOATS * 4)

// barrier byte offsets (from smem base)
#define B_A ((OFF_MBAR + 0) * 4)
#define B_B ((OFF_MBAR + 2) * 4)
#define B_C ((OFF_MBAR + 4) * 4)
#define B_D ((OFF_MBAR + 6) * 4)

// tx bytes per barrier per phase per CTA: 16 lanes x 8 source CTAs x 4B
#define TXB 512

// fused store+signal to all 8 CTAs (data and completion in one transaction)
__device__ __forceinline__ void bcast_async(const uint32_t* rb, uint32_t doff,
                                            float v, uint32_t boff) {
    uint32_t vb = __float_as_uint(v);
#pragma unroll
    for (int rk = 0; rk < NCTA; rk++)
        asm volatile("st.async.shared::cluster.mbarrier::complete_tx::bytes.b32 [%0], %1, [%2];"
                     :: "r"(rb[rk] + doff), "r"(vb), "r"(rb[rk] + boff) : "memory");
}

__device__ __forceinline__ void mbar_wait(uint32_t mbar, uint32_t ph) {
    asm volatile(
        "{\n\t"
        ".reg .pred P;\n\t"
        "WL_%=:\n\t"
        "mbarrier.try_wait.parity.acquire.cluster.shared::cta.b64 P, [%0], %1, 0x989680;\n\t"
        "@P bra.uni WD_%=;\n\t"
        "bra.uni WL_%=;\n\t"
        "WD_%=:\n\t"
        "}"
        :: "r"(mbar), "r"(ph) : "memory");
}

#define EXPECT_TX(boff) \
    asm volatile("mbarrier.arrive.expect_tx.shared.b64 _, [%0], %1;" \
                 :: "r"(sbase + (boff)), "r"((uint32_t)TXB) : "memory")

__global__ void __launch_bounds__(TPB, 1) __cluster_dims__(NCTA, 1, 1)
k_scan(const float* __restrict__ out0, const float* __restrict__ h0in,
       const float* __restrict__ c0in,
       const float* __restrict__ Wi2h, const float* __restrict__ Wh2h,
       const float* __restrict__ bh2h_g,
       const float* __restrict__ Wh2o, const float* __restrict__ bh2o_g,
       const float* __restrict__ Wih0, const float* __restrict__ Whh0,
       const float* __restrict__ bih0, const float* __restrict__ bhh0,
       const float* __restrict__ Wih1, const float* __restrict__ Whh1,
       const float* __restrict__ bih1, const float* __restrict__ bhh1,
       const float* __restrict__ Wih2, const float* __restrict__ Whh2,
       const float* __restrict__ bih2, const float* __restrict__ bhh2,
       float* __restrict__ dout, int out_size) {
    extern __shared__ float sm[];
    const int tid  = threadIdx.x;
    const int rank = blockIdx.x;
    const unsigned FULL = 0xffffffffu;
    const uint32_t sbase = (uint32_t)__cvta_generic_to_shared(sm);

    float* l0w   = sm + OFF_L0W;
    float* l1w   = sm + OFF_L1W;
    float* l2w   = sm + OFF_L2W;
    float* wd    = sm + OFF_WD;
    float* bhhf  = sm + OFF_BHH;
    float* bh2o  = sm + OFF_BH2O;
    float* h0b   = sm + OFF_H0;
    float* h1b   = sm + OFF_H1;
    float* h2b   = sm + OFF_H2;
    float* hD    = sm + OFF_HD;
    float* hidE  = sm + OFF_HE;
    float* hidF  = sm + OFF_HF;
    float* obuf  = sm + OFF_OBUF;

    const int j     = tid >> 4;        // 0..15
    const int g     = (tid >> 2) & 3;  // gate
    const int cs    = tid & 3;         // 32-col slice
    const int sub16 = tid & 15;
    const int lane  = tid & 31;
    const int base  = lane & ~15;      // j-group start within warp

    // remote smem base of every cluster CTA (mapa hoisted out of the loop)
    uint32_t rb[NCTA];
#pragma unroll
    for (int rk = 0; rk < NCTA; rk++)
        asm("mapa.shared::cluster.u32 %0, %1, %2;" : "=r"(rb[rk]) : "r"(sbase), "r"(rk));

    // mbarrier init: count=1 (the expect_tx arrive); completion = 512B tx
    if (tid == 0) {
#pragma unroll
        for (int b = 0; b < 4; b++)
            asm volatile("mbarrier.init.shared.b64 [%0], %1;"
                         :: "r"(sbase + B_A + 8u * b), "r"(1) : "memory");
        EXPECT_TX(B_A); EXPECT_TX(B_B); EXPECT_TX(B_C); EXPECT_TX(B_D);
    }

    // ---------------- load LSTM weight slices ----------------
    for (int idx = tid; idx < 16384; idx += TPB) {
        int s = idx >> 10, rem = idx & 1023;
        int t = rem >> 2, c = rem & 3;
        int jj = t >> 4, gg = (t >> 2) & 3, cc = t & 3;
        int R = gg * 128 + rank * 16 + jj;
        int col = cc * 32 + (s & 7) * 4 + c;
        if (s < 8) {
            l1w[idx] = Wih1[(size_t)R * 128 + col];
            l2w[idx] = Wih2[(size_t)R * 128 + col];
        } else {
            l1w[idx] = Whh1[(size_t)R * 128 + col];
            l2w[idx] = Whh2[(size_t)R * 128 + col];
        }
    }
    for (int idx = tid; idx < 11264; idx += TPB) {
        int s = idx >> 10, rem = idx & 1023;
        int t = rem >> 2, c = rem & 3;
        int jj = t >> 4, gg = (t >> 2) & 3, cc = t & 3;
        int R = gg * 128 + rank * 16 + jj;
        float v;
        if (s < 3) v = (cc == 0) ? Wih0[(size_t)R * 12 + s * 4 + c] : 0.f;
        else       v = Whh0[(size_t)R * 128 + cc * 32 + (s - 3) * 4 + c];
        l0w[idx] = v;
    }
    for (int idx = tid; idx < 2048; idx += TPB) {
        int c = idx >> 10, rem = idx & 1023, t = rem >> 2, e = rem & 3;
        int r = t >> 4, sb = t & 15;
        wd[idx] = Wi2h[(size_t)(rank * 16 + r) * 1152 + 1024 + sb * 8 + c * 4 + e];
    }
    if (tid < 128) {
        bhhf[tid] = bh2h_g[tid];
        h0b[128 + tid] = h0in[tid];
        h1b[128 + tid] = h0in[128 + tid];
        h2b[128 + tid] = h0in[256 + tid];
    }
    if (tid < 12) { bh2o[tid] = bh2o_g[tid]; obuf[tid] = out0[tid]; }
    if (tid >= 12 && tid < 16) obuf[tid] = 0.f;

    // per-thread fused biases (all lanes; added after column-combine)
    float bA, bB, bC;
    {
        int R = g * 128 + rank * 16 + j;
        bA = bih0[R] + bhh0[R];
        bB = bih1[R] + bhh1[R];
        bC = bih2[R] + bhh2[R];
    }
    // cell state lives in producer-lane registers
    float cA = 0.f, cB = 0.f, cC = 0.f;
    if (sub16 == 0) {
        cA = c0in[0 * 128 + rank * 16 + j];
        cB = c0in[1 * 128 + rank * 16 + j];
        cC = c0in[2 * 128 + rank * 16 + j];
    }
    // E/F weights: half a Wh2h row per thread, in registers
    float4 wreg[16];
#pragma unroll
    for (int k = 0; k < 16; k++)
        wreg[k] = *(const float4*)&Wh2h[(size_t)(tid >> 1) * 128 + (tid & 1) * 64 + k * 4];
    // G weights: 8 cols of one Wh2o row per thread (tid<192)
    float4 gwreg[2] = {};
    if (tid < 192) {
#pragma unroll
        for (int c = 0; c < 2; c++)
            gwreg[c] = *(const float4*)&Wh2o[(size_t)(tid >> 4) * 128 + sub16 * 8 + c * 4];
    }

    __syncthreads();
    CLUSTER_SYNC();   // all SMEM + mbarrier init visible cluster-wide

    const float4* W0 = (const float4*)l0w;
    const float4* W1 = (const float4*)l1w;
    const float4* W2 = (const float4*)l2w;
    const float4* WD = (const float4*)wd;

    // macro: combine 4 col-lanes, add bias, parallel per-gate activation,
    // gather activated f/g/o into the producer lane, update c, broadcast h
    #define GATE_TAIL(BIAS, CREG, DOFF, BOFF) do {                              \
        float acc = (a0 + a1) + (a2 + a3);                                      \
        acc += __shfl_xor_sync(FULL, acc, 1);                                   \
        acc += __shfl_xor_sync(FULL, acc, 2);                                   \
        acc += (BIAS);                                                          \
        float xs = (g == 2) ? acc : 0.5f * acc;                                 \
        float tv = tanha(xs);                                                   \
        float act = (g == 2) ? tv : fmaf(0.5f, tv, 0.5f);                       \
        float fac = __shfl_sync(FULL, act, base + 4);                           \
        float gac = __shfl_sync(FULL, act, base + 8);                           \
        float oac = __shfl_sync(FULL, act, base + 12);                          \
        if (sub16 == 0) {                                                       \
            CREG = fmaf(fac, CREG, act * gac);                                  \
            bcast_async(rb, (DOFF) * 4u, oac * tanha(CREG), BOFF);              \
        }                                                                       \
    } while (0)

    // ---------------- prologue: stage A of step 0 ----------------
    {
        const float4* hv = (const float4*)(h0b + 128 + cs * 32);  // parity-1 init
        float a0 = 0, a1 = 0, a2 = 0, a3 = 0;
#pragma unroll
        for (int k = 0; k < 8; k++) { float4 wv = W0[((3 + k) << 8) + tid]; FMA4(wv, hv[k]); }
        if (cs == 0) {
            const float4* ob4 = (const float4*)obuf;
#pragma unroll
            for (int k = 0; k < 3; k++) { float4 wv = W0[(k << 8) + tid]; FMA4(wv, ob4[k]); }
        }
        GATE_TAIL(bA, cA, OFF_H0 + 0 + rank * 16 + j, B_A);
    }

    // ---------------- main scan ----------------
#pragma unroll 1
    for (int t = 0; t < STEPS; t++) {
        const int p = t & 1, q = p ^ 1;
        const uint32_t ph = (uint32_t)(t & 1);
        float* h0w = h0b + p * 128;
        float* h1w = h1b + p * 128; const float* h1r = h1b + q * 128;
        float* h2w = h2b + p * 128; const float* h2r = h2b + q * 128;

        float pre_r = 0.f;
        if (sub16 == 0) pre_r = g_pre[(size_t)t * HDIM + rank * 16 + j];

        // ======== stage B: LSTM layer 1 — hh half hoisted over wait_A ========
        float a0 = 0, a1 = 0, a2 = 0, a3 = 0;
        {
            const float4* pv = (const float4*)(h1r + cs * 32);
#pragma unroll
            for (int k = 0; k < 8; k++) { float4 wv = W1[((8 + k) << 8) + tid]; FMA4(wv, pv[k]); }
        }
        mbar_wait(sbase + B_A, ph);             // h0(t) ready everywhere
        if (tid == 0) EXPECT_TX(B_A);           // re-arm for phase t+1
        {
            const float4* xv = (const float4*)(h0w + cs * 32);
#pragma unroll
            for (int k = 0; k < 8; k++) { float4 wv = W1[(k << 8) + tid]; FMA4(wv, xv[k]); }
        }
        GATE_TAIL(bB, cB, OFF_H1 + p * 128 + rank * 16 + j, B_B);

        // ======== stage C: LSTM layer 2 — hh half hoisted over wait_B ========
        a0 = 0; a1 = 0; a2 = 0; a3 = 0;
        {
            const float4* pv = (const float4*)(h2r + cs * 32);
#pragma unroll
            for (int k = 0; k < 8; k++) { float4 wv = W2[((8 + k) << 8) + tid]; FMA4(wv, pv[k]); }
        }
        mbar_wait(sbase + B_B, ph);             // h1(t) ready
        if (tid == 0) EXPECT_TX(B_B);
        {
            const float4* xv = (const float4*)(h1w + cs * 32);
#pragma unroll
            for (int k = 0; k < 8; k++) { float4 wv = W2[(k << 8) + tid]; FMA4(wv, xv[k]); }
        }
        GATE_TAIL(bC, cC, OFF_H2 + p * 128 + rank * 16 + j, B_C);
        mbar_wait(sbase + B_C, ph);             // h2(t) ready
        if (tid == 0) EXPECT_TX(B_C);

        // ======== stage D: hid = tanh(pre + Wi2h_h @ h2) — distributed ========
        {
            const float4* hx = (const float4*)(h2w + sub16 * 8);
            float d0 = 0, d1 = 0, d2 = 0, d3 = 0;
#pragma unroll
            for (int c = 0; c < 2; c++) {
                float4 wv = WD[(c << 8) + tid];
                d0 = fmaf(wv.x, hx[c].x, d0); d1 = fmaf(wv.y, hx[c].y, d1);
                d2 = fmaf(wv.z, hx[c].z, d2); d3 = fmaf(wv.w, hx[c].w, d3);
            }
            float acc = (d0 + d1) + (d2 + d3);
            acc += __shfl_xor_sync(FULL, acc, 1);
            acc += __shfl_xor_sync(FULL, acc, 2);
            acc += __shfl_xor_sync(FULL, acc, 4);
            acc += __shfl_xor_sync(FULL, acc, 8);
            if (sub16 == 0)
                bcast_async(rb, (OFF_HD + rank * 16 + j) * 4u, tanha(acc + pre_r), B_D);
        }

        // ======== stage A (step t+1) hh-half — hides wait_D ========
        a0 = 0; a1 = 0; a2 = 0; a3 = 0;
        if (t < STEPS - 1) {
            const float4* hv = (const float4*)(h0w + cs * 32);  // h0(t)
#pragma unroll
            for (int k = 0; k < 8; k++) { float4 wv = W0[((3 + k) << 8) + tid]; FMA4(wv, hv[k]); }
        }
        mbar_wait(sbase + B_D, ph);             // hD full ready
        if (tid == 0) EXPECT_TX(B_D);

        // ======== stages E/F: redundant local (reg-resident half-rows) ========
        {
            const float4* xv = (const float4*)(hD + (tid & 1) * 64);
            float e0 = 0, e1 = 0, e2 = 0, e3 = 0;
#pragma unroll
            for (int k = 0; k < 16; k++) {
                e0 = fmaf(wreg[k].x, xv[k].x, e0); e1 = fmaf(wreg[k].y, xv[k].y, e1);
                e2 = fmaf(wreg[k].z, xv[k].z, e2); e3 = fmaf(wreg[k].w, xv[k].w, e3);
            }
            float acc = (e0 + e1) + (e2 + e3);
            acc += __shfl_xor_sync(FULL, acc, 1);
            if ((tid & 1) == 0)
                hidE[tid >> 1] = fmaxf(acc + bhhf[tid >> 1], 0.f);
        }
        __syncthreads();
        {
            const float4* xv = (const float4*)(hidE + (tid & 1) * 64);
            float e0 = 0, e1 = 0, e2 = 0, e3 = 0;
#pragma unroll
            for (int k = 0; k < 16; k++) {
                e0 = fmaf(wreg[k].x, xv[k].x, e0); e1 = fmaf(wreg[k].y, xv[k].y, e1);
                e2 = fmaf(wreg[k].z, xv[k].z, e2); e3 = fmaf(wreg[k].w, xv[k].w, e3);
            }
            float acc = (e0 + e1) + (e2 + e3);
            acc += __shfl_xor_sync(FULL, acc, 1);
            if ((tid & 1) == 0)
                hidF[tid >> 1] = fmaxf(acc + bhhf[tid >> 1], 0.f);
        }
        __syncthreads();
        // ======== stage G: o = sigmoid(Wh2o @ hid + b) — redundant per CTA ====
        if (tid < 192) {
            const float4* xv = (const float4*)(hidF + sub16 * 8);
            float e0 = 0, e1 = 0, e2 = 0, e3 = 0;
#pragma unroll
            for (int c = 0; c < 2; c++) {
                e0 = fmaf(gwreg[c].x, xv[c].x, e0); e1 = fmaf(gwreg[c].y, xv[c].y, e1);
                e2 = fmaf(gwreg[c].z, xv[c].z, e2); e3 = fmaf(gwreg[c].w, xv[c].w, e3);
            }
            float acc = (e0 + e1) + (e2 + e3);
            acc += __shfl_xor_sync(FULL, acc, 1);
            acc += __shfl_xor_sync(FULL, acc, 2);
            acc += __shfl_xor_sync(FULL, acc, 4);
            acc += __shfl_xor_sync(FULL, acc, 8);
            if (sub16 == 0) {
                int r = tid >> 4;  // 0..11
                float ov = sigm(acc + bh2o[r]);
                obuf[r] = ov;
                if (rank == 0) dout[(size_t)t * ODIM + r] = ov;
            }
        }
        __syncthreads();

        // ======== stage A (step t+1) tail: obuf part + gates + bcast ========
        if (t < STEPS - 1) {
            if (cs == 0) {
                const float4* ob4 = (const float4*)obuf;
#pragma unroll
                for (int k = 0; k < 3; k++) { float4 wv = W0[(k << 8) + tid]; FMA4(wv, ob4[k]); }
            }
            GATE_TAIL(bA, cA, OFF_H0 + q * 128 + rank * 16 + j, B_A);
        }
    }

    // ---------------- final hN / cN ----------------
    if (out_size >= STEPS * ODIM + 6 * HDIM) {
        const int fb = STEPS * ODIM;  // 49152
        if (rank == 0 && tid < 128) {
            dout[fb + tid]       = h0b[128 + tid];  // final parity = 1
            dout[fb + 128 + tid] = h1b[128 + tid];
            dout[fb + 256 + tid] = h2b[128 + tid];
        }
        if (sub16 == 0) {
            dout[fb + 384 + 0 * 128 + rank * 16 + j] = cA;
            dout[fb + 384 + 1 * 128 + rank * 16 + j] = cB;
            dout[fb + 384 + 2 * 128 + rank * 16 + j] = cC;
        }
    }
}

// =====================================================================
// launch
// =====================================================================
extern "C" void kernel_launch(void* const* d_in, const int* in_sizes, int n_in,
                              void* d_out, int out_size) {
    const float* inputs = (const float*)d_in[0];
    const float* out0   = (const float*)d_in[1];
    const float* h0in   = (const float*)d_in[2];
    const float* c0in   = (const float*)d_in[3];
    const float* W_s2i  = (const float*)d_in[4];
    const float* b_s2i  = (const float*)d_in[5];
    const float* W_i2h  = (const float*)d_in[6];
    const float* b_i2h  = (const float*)d_in[7];
    const float* W_h2h  = (const float*)d_in[8];
    const float* b_h2h  = (const float*)d_in[9];
    const float* W_h2o  = (const float*)d_in[10];
    const float* b_h2o  = (const float*)d_in[11];
    const float* Wih0   = (const float*)d_in[12];
    const float* Whh0   = (const float*)d_in[13];
    const float* bih0   = (const float*)d_in[14];
    const float* bhh0   = (const float*)d_in[15];
    const float* Wih1   = (const float*)d_in[16];
    const float* Whh1   = (const float*)d_in[17];
    const float* bih1   = (const float*)d_in[18];
    const float* bhh1   = (const float*)d_in[19];
    const float* Wih2   = (const float*)d_in[20];
    const float* Whh2   = (const float*)d_in[21];
    const float* bih2   = (const float*)d_in[22];
    const float* bhh2   = (const float*)d_in[23];
    float* dout = (float*)d_out;

    cudaFuncSetAttribute(k_scan, cudaFuncAttributeMaxDynamicSharedMemorySize, SMEM_BYTES);

    k_cf<<<1, 128>>>(b_s2i, W_i2h, b_i2h);
    k_mt<<<dim3(DATA / 256, HDIM / 16), 256>>>(W_s2i, W_i2h);
    k_pre<<<STEPS / 16, 256>>>(inputs);
    k_scan<<<NCTA, TPB, SMEM_BYTES>>>(out0, h0in, c0in,
                                      W_i2h, W_h2h, b_h2h, W_h2o, b_h2o,
                                      Wih0, Whh0, bih0, bhh0,
                                      Wih1, Whh1, bih1, bhh1,
                                      Wih2, Whh2, bih2, bhh2,
                                      dout, out_size);
}

// round 13
// speedup vs baseline: 1.7319x; 1.7319x over previous
#include <cuda_runtime.h>
#include <cstdint>

// ---------------- problem constants ----------------
#define STEPS 4096
#define DATA  8192
#define EMBD  1024
#define HDIM  128
#define ODIM  12
#define NCTA  8
#define TPB   128

// ---------------- device scratch (no allocations allowed) ----------------
__device__ float g_Mt[(size_t)DATA * HDIM];     // fused weight Mt[d][i]  (4 MB)
__device__ float g_pre[(size_t)STEPS * HDIM];   // pre_i2h[t][i] + c_fused (2 MB)
__device__ float g_cf[HDIM];                    // fused bias

__device__ __forceinline__ float tanha(float x) {
    float y; asm("tanh.approx.f32 %0, %1;" : "=f"(y) : "f"(x)); return y;
}
__device__ __forceinline__ float sigm(float x) { return 0.5f + 0.5f * tanha(0.5f * x); }

#define CLUSTER_SYNC() do { \
  asm volatile("barrier.cluster.arrive.aligned;" ::: "memory"); \
  asm volatile("barrier.cluster.wait.aligned;"   ::: "memory"); } while (0)

// NOTE: parameter names must not collide with float4 member tokens x/y/z/w
#define FMA4(W_, X_) do { a0 = fmaf((W_).x,(X_).x,a0); a1 = fmaf((W_).y,(X_).y,a1); \
                          a2 = fmaf((W_).z,(X_).z,a2); a3 = fmaf((W_).w,(X_).w,a3); } while (0)

// =====================================================================
// K0: c_fused[i] = b_i2h[i] + sum_e b_s2i[e] * W_i2h[i][e]
// =====================================================================
__global__ void k_cf(const float* __restrict__ b_s2i,
                     const float* __restrict__ Wi2h,
                     const float* __restrict__ b_i2h) {
    int i = threadIdx.x;  // 128 threads
    const float4* b4 = (const float4*)b_s2i;
    const float4* w4 = (const float4*)(Wi2h + (size_t)i * 1152);
    float a0 = 0, a1 = 0, a2 = 0, a3 = 0;
    for (int k = 0; k < EMBD / 4; k++) { float4 bv = b4[k], wv = w4[k]; FMA4(wv, bv); }
    g_cf[i] = b_i2h[i] + ((a0 + a1) + (a2 + a3));
}

// =====================================================================
// K1: Mt[d][i] = sum_e Ws2i[e][d] * Wi2h[i][e]     grid(32,8), 256 thr
// =====================================================================
__global__ void __launch_bounds__(256) k_mt(const float* __restrict__ Ws2i,
                                            const float* __restrict__ Wi2h) {
    __shared__ float we[16][128];
    int d  = blockIdx.x * 256 + threadIdx.x;
    int i0 = blockIdx.y * 16;
    float acc[16];
#pragma unroll
    for (int ii = 0; ii < 16; ii++) acc[ii] = 0.f;
    for (int e0 = 0; e0 < EMBD; e0 += 128) {
#pragma unroll
        for (int k = 0; k < 8; k++) {
            int idx = k * 256 + threadIdx.x;
            int ii = idx >> 7, ee = idx & 127;
            we[ii][ee] = Wi2h[(size_t)(i0 + ii) * 1152 + e0 + ee];
        }
        __syncthreads();
        for (int ee = 0; ee < 128; ee++) {
            float ws = Ws2i[(size_t)(e0 + ee) * DATA + d];
#pragma unroll
            for (int ii = 0; ii < 16; ii++) acc[ii] = fmaf(we[ii][ee], ws, acc[ii]);
        }
        __syncthreads();
    }
#pragma unroll
    for (int ii = 0; ii < 16; ii++) g_Mt[(size_t)d * HDIM + i0 + ii] = acc[ii];
}

// =====================================================================
// K2: pre[t][i] = c_fused[i] + sum_d inputs[t][d] * Mt[d][i]
// =====================================================================
__global__ void __launch_bounds__(256) k_pre(const float* __restrict__ inputs) {
    __shared__ float xin[16 * 64];
    __shared__ float wm[64 * 128];
    int t0   = blockIdx.x * 16;
    int i    = threadIdx.x & 127;
    int trow = threadIdx.x >> 7;  // 0..1
    float acc[8];
#pragma unroll
    for (int k = 0; k < 8; k++) acc[k] = 0.f;
    for (int d0 = 0; d0 < DATA; d0 += 64) {
        {
            int idx = threadIdx.x * 4;
            int tt = idx >> 6, dd = idx & 63;
            *(float4*)&xin[idx] = *(const float4*)&inputs[(size_t)(t0 + tt) * DATA + d0 + dd];
        }
#pragma unroll
        for (int k = 0; k < 8; k++) {
            int x4 = (k * 256 + threadIdx.x) * 4;
            *(float4*)&wm[x4] = *(const float4*)&g_Mt[(size_t)d0 * HDIM + x4];
        }
        __syncthreads();
        for (int dd = 0; dd < 64; dd++) {
            float m = wm[dd * 128 + i];
#pragma unroll
            for (int tt = 0; tt < 8; tt++)
                acc[tt] = fmaf(xin[(trow + tt * 2) * 64 + dd], m, acc[tt]);
        }
        __syncthreads();
    }
    float cf = g_cf[i];
#pragma unroll
    for (int tt = 0; tt < 8; tt++)
        g_pre[(size_t)(t0 + trow + tt * 2) * HDIM + i] = acc[tt] + cf;
}

// =====================================================================
// K3: the sequential scan — 8-CTA cluster, 128 thr/CTA, mbarrier p2p sync
//  (R11 fabric: st.shared::cluster + per-producer arrives, count=128)
// =====================================================================
#define OFF_L0W   0         /* 9728  */
#define OFF_L1W   9728      /* 16384 */
#define OFF_L2W   26112     /* 16384 */
#define OFF_WD    42496     /* 2048  */
#define OFF_BHH   44544     /* 128   */
#define OFF_BH2O  44672     /* 16    */
#define OFF_H0    44688     /* 256   */
#define OFF_H1    44944     /* 256   */
#define OFF_H2    45200     /* 256   */
#define OFF_HD    45456     /* 128   */
#define OFF_HE    45584     /* 128   */
#define OFF_HF    45712     /* 128   */
#define OFF_OBUF  45840     /* 16    */
#define OFF_WO    45856     /* 1536  */
#define OFF_MBAR  47392     /* 4 mbarriers = 8 floats (8B aligned) */
#define SMEM_FLOATS 47400
#define SMEM_BYTES  (SMEM_FLOATS * 4)

// barrier byte offsets (from smem base)
#define B_A ((OFF_MBAR + 0) * 4)
#define B_B ((OFF_MBAR + 2) * 4)
#define B_C ((OFF_MBAR + 4) * 4)
#define B_D ((OFF_MBAR + 6) * 4)

// store v into all 8 CTAs at byte offset doff, then arrive on each CTA's
// mbarrier at byte offset boff (release orders the store before the arrive)
__device__ __forceinline__ void bcast_arrive(const uint32_t* rb, uint32_t doff,
                                             float v, uint32_t boff) {
    uint32_t vb = __float_as_uint(v);
#pragma unroll
    for (int rk = 0; rk < NCTA; rk++)
        asm volatile("st.shared::cluster.u32 [%0], %1;" :: "r"(rb[rk] + doff), "r"(vb) : "memory");
#pragma unroll
    for (int rk = 0; rk < NCTA; rk++)
        asm volatile("mbarrier.arrive.shared::cluster.b64 _, [%0];" :: "r"(rb[rk] + boff) : "memory");
}

__device__ __forceinline__ void mbar_wait(uint32_t mbar, uint32_t ph) {
    asm volatile(
        "{\n\t"
        ".reg .pred P;\n\t"
        "WL_%=:\n\t"
        "mbarrier.try_wait.parity.acquire.cluster.shared::cta.b64 P, [%0], %1, 0x989680;\n\t"
        "@P bra.uni WD_%=;\n\t"
        "bra.uni WL_%=;\n\t"
        "WD_%=:\n\t"
        "}"
        :: "r"(mbar), "r"(ph) : "memory");
}

__global__ void __launch_bounds__(TPB, 1) __cluster_dims__(NCTA, 1, 1)
k_scan(const float* __restrict__ out0, const float* __restrict__ h0in,
       const float* __restrict__ c0in,
       const float* __restrict__ Wi2h, const float* __restrict__ Wh2h,
       const float* __restrict__ bh2h_g,
       const float* __restrict__ Wh2o, const float* __restrict__ bh2o_g,
       const float* __restrict__ Wih0, const float* __restrict__ Whh0,
       const float* __restrict__ bih0, const float* __restrict__ bhh0,
       const float* __restrict__ Wih1, const float* __restrict__ Whh1,
       const float* __restrict__ bih1, const float* __restrict__ bhh1,
       const float* __restrict__ Wih2, const float* __restrict__ Whh2,
       const float* __restrict__ bih2, const float* __restrict__ bhh2,
       float* __restrict__ dout, int out_size) {
    extern __shared__ float sm[];
    const int tid  = threadIdx.x;
    const int rank = blockIdx.x;
    const unsigned FULL = 0xffffffffu;
    const uint32_t sbase = (uint32_t)__cvta_generic_to_shared(sm);

    float* l0w   = sm + OFF_L0W;
    float* l1w   = sm + OFF_L1W;
    float* l2w   = sm + OFF_L2W;
    float* wd    = sm + OFF_WD;
    float* bhhf  = sm + OFF_BHH;
    float* bh2o  = sm + OFF_BH2O;
    float* h0b   = sm + OFF_H0;
    float* h1b   = sm + OFF_H1;
    float* h2b   = sm + OFF_H2;
    float* hD    = sm + OFF_HD;
    float* hidE  = sm + OFF_HE;
    float* hidF  = sm + OFF_HF;
    float* obuf  = sm + OFF_OBUF;
    float* wo    = sm + OFF_WO;

    const int j    = tid >> 3;
    const int g    = (tid >> 1) & 3;
    const int cs   = tid & 1;
    const int oct  = tid & 7;
    const int lane = tid & 31;
    const int base = lane & ~7;

    // remote smem base of every cluster CTA (mapa hoisted out of the loop)
    uint32_t rb[NCTA];
#pragma unroll
    for (int rk = 0; rk < NCTA; rk++)
        asm("mapa.shared::cluster.u32 %0, %1, %2;" : "=r"(rb[rk]) : "r"(sbase), "r"(rk));

    // mbarrier init (count = 16 producer lanes * 8 CTAs = 128)
    if (tid == 0) {
#pragma unroll
        for (int b = 0; b < 4; b++)
            asm volatile("mbarrier.init.shared.b64 [%0], %1;"
                         :: "r"(sbase + B_A + 8u * b), "r"(128) : "memory");
    }

    // ---------------- load LSTM weight slices ----------------
    for (int idx = tid; idx < 16384; idx += TPB) {
        int s = idx >> 9, rem = idx & 511;
        int t = rem >> 2, c = rem & 3;
        int p = s >> 4, k = s & 15;
        int jj = t >> 3, gg = (t >> 1) & 3, cc = t & 1;
        int R = gg * 128 + rank * 16 + jj;
        int col = cc * 64 + k * 4 + c;
        l1w[idx] = p ? Whh1[(size_t)R * 128 + col] : Wih1[(size_t)R * 128 + col];
        l2w[idx] = p ? Whh2[(size_t)R * 128 + col] : Wih2[(size_t)R * 128 + col];
    }
    for (int idx = tid; idx < 9728; idx += TPB) {
        int s = idx >> 9, rem = idx & 511;
        int t = rem >> 2, c = rem & 3;
        int jj = t >> 3, gg = (t >> 1) & 3, cc = t & 1;
        int R = gg * 128 + rank * 16 + jj;
        float v;
        if (s < 3) v = (cc == 0) ? Wih0[(size_t)R * 12 + s * 4 + c] : 0.f;
        else       v = Whh0[(size_t)R * 128 + cc * 64 + (s - 3) * 4 + c];
        l0w[idx] = v;
    }
    for (int idx = tid; idx < 2048; idx += TPB) {
        int c = idx >> 9, rem = idx & 511, t = rem >> 2, e = rem & 3;
        int r = t >> 3, oc = t & 7;
        wd[idx] = Wi2h[(size_t)(rank * 16 + r) * 1152 + 1024 + oc * 16 + c * 4 + e];
    }
    // G-stage weights in interleaved SMEM (96 active lanes, conflict-free)
    for (int idx = tid; idx < 1536; idx += TPB) {
        int c = idx / 384, rem = idx % 384;
        int t = rem >> 2, e = rem & 3;
        int r = t >> 3, oc = t & 7;
        wo[idx] = Wh2o[(size_t)r * 128 + oc * 16 + c * 4 + e];
    }
    bhhf[tid] = bh2h_g[tid];
    if (tid < 12) { bh2o[tid] = bh2o_g[tid]; obuf[tid] = out0[tid]; }
    if (tid >= 12 && tid < 16) obuf[tid] = 0.f;
    h0b[128 + tid] = h0in[tid];
    h1b[128 + tid] = h0in[128 + tid];
    h2b[128 + tid] = h0in[256 + tid];

    float bA = 0.f, bB = 0.f, bC = 0.f;
    {
        int R = g * 128 + rank * 16 + j;
        if (cs == 0) {
            bA = bih0[R] + bhh0[R];
            bB = bih1[R] + bhh1[R];
            bC = bih2[R] + bhh2[R];
        }
    }
    float cA = 0.f, cB = 0.f, cC = 0.f;
    if (oct == 0) {
        cA = c0in[0 * 128 + rank * 16 + j];
        cB = c0in[1 * 128 + rank * 16 + j];
        cC = c0in[2 * 128 + rank * 16 + j];
    }
    // E/F weights permanently in registers
    float4 wreg[32];
#pragma unroll
    for (int k = 0; k < 32; k++)
        wreg[k] = *(const float4*)&Wh2h[(size_t)tid * 128 + k * 4];

    __syncthreads();
    CLUSTER_SYNC();   // all SMEM init + mbarrier init visible cluster-wide

    const float4* W0 = (const float4*)l0w;
    const float4* W1 = (const float4*)l1w;
    const float4* W2 = (const float4*)l2w;
    const float4* WD = (const float4*)wd;
    const float4* WO4 = (const float4*)wo;

    // parallel-activation gate tail: every lane activates its own gate, the
    // producer lane gathers activated f/g/o, updates c, broadcasts h.
    #define GATE_TAIL(BIAS, CREG, DOFF, BOFF) do {                              \
        float acc = (a0 + a1) + (a2 + a3);                                      \
        acc += __shfl_xor_sync(FULL, acc, 1);                                   \
        acc += (BIAS);                                                          \
        acc = __shfl_sync(FULL, acc, base + g * 2);  /* cs0 value to both */    \
        float xs = (g == 2) ? acc : 0.5f * acc;                                 \
        float tv = tanha(xs);                                                   \
        float act = (g == 2) ? tv : fmaf(0.5f, tv, 0.5f);                       \
        float fac = __shfl_sync(FULL, act, base + 2);                           \
        float gac = __shfl_sync(FULL, act, base + 4);                           \
        float oac = __shfl_sync(FULL, act, base + 6);                           \
        if (oct == 0) {                                                         \
            CREG = fmaf(fac, CREG, act * gac);                                  \
            bcast_arrive(rb, (DOFF) * 4u, oac * tanha(CREG), BOFF);             \
        }                                                                       \
    } while (0)

    // ---------------- prologue: stage A of step 0 ----------------
    {
        const float4* hv = (const float4*)(h0b + 128 + cs * 64);  // parity 1 init
        float a0 = 0, a1 = 0, a2 = 0, a3 = 0;
#pragma unroll
        for (int k = 0; k < 16; k++) { float4 wv = W0[((3 + k) << 7) + tid]; FMA4(wv, hv[k]); }
        if (cs == 0) {
            const float4* ob4 = (const float4*)obuf;
#pragma unroll
            for (int k = 0; k < 3; k++) { float4 wv = W0[(k << 7) + tid]; FMA4(wv, ob4[k]); }
        }
        GATE_TAIL(bA, cA, OFF_H0 + 0 + rank * 16 + j, B_A);
    }

    // ---------------- main scan ----------------
#pragma unroll 1
    for (int t = 0; t < STEPS; t++) {
        const int p = t & 1, q = p ^ 1;
        const uint32_t ph = (uint32_t)(t & 1);
        float* h0w = h0b + p * 128;
        float* h1w = h1b + p * 128; const float* h1r = h1b + q * 128;
        float* h2w = h2b + p * 128; const float* h2r = h2b + q * 128;

        float pre_r = 0.f;
        if (oct == 0) pre_r = g_pre[(size_t)t * HDIM + rank * 16 + j];

        // ======== stage B: LSTM layer 1 — hh half hoisted over wait_A ========
        float a0 = 0, a1 = 0, a2 = 0, a3 = 0;
        {
            const float4* pv = (const float4*)(h1r + cs * 64);
#pragma unroll
            for (int k = 0; k < 16; k++) { float4 wv = W1[((16 + k) << 7) + tid]; FMA4(wv, pv[k]); }
        }
        mbar_wait(sbase + B_A, ph);             // h0(t) ready everywhere
        {
            const float4* xv = (const float4*)(h0w + cs * 64);
#pragma unroll
            for (int k = 0; k < 16; k++) { float4 wv = W1[(k << 7) + tid]; FMA4(wv, xv[k]); }
        }
        GATE_TAIL(bB, cB, OFF_H1 + p * 128 + rank * 16 + j, B_B);

        // ======== stage C: LSTM layer 2 — hh half hoisted over wait_B ========
        a0 = 0; a1 = 0; a2 = 0; a3 = 0;
        {
            const float4* pv = (const float4*)(h2r + cs * 64);
#pragma unroll
            for (int k = 0; k < 16; k++) { float4 wv = W2[((16 + k) << 7) + tid]; FMA4(wv, pv[k]); }
        }
        mbar_wait(sbase + B_B, ph);             // h1(t) ready
        {
            const float4* xv = (const float4*)(h1w + cs * 64);
#pragma unroll
            for (int k = 0; k < 16; k++) { float4 wv = W2[(k << 7) + tid]; FMA4(wv, xv[k]); }
        }
        GATE_TAIL(bC, cC, OFF_H2 + p * 128 + rank * 16 + j, B_C);

        // ======== stage A (step t+1) hh-half part 1 — hides wait_C ========
        float n0 = 0, n1 = 0, n2 = 0, n3 = 0;
        if (t < STEPS - 1) {
            const float4* hv = (const float4*)(h0w + cs * 64);  // h0(t), acquired
#pragma unroll
            for (int k = 0; k < 8; k++) {
                float4 wv = W0[((3 + k) << 7) + tid];
                float4 xq = hv[k];
                n0 = fmaf(wv.x, xq.x, n0); n1 = fmaf(wv.y, xq.y, n1);
                n2 = fmaf(wv.z, xq.z, n2); n3 = fmaf(wv.w, xq.w, n3);
            }
        }
        mbar_wait(sbase + B_C, ph);             // h2(t) ready

        // ======== stage D: hid = tanh(pre + Wi2h_h @ h2) — distributed ========
        {
            const float4* hx = (const float4*)(h2w + oct * 16);
            float d0 = 0, d1 = 0, d2 = 0, d3 = 0;
#pragma unroll
            for (int c = 0; c < 4; c++) {
                float4 wv = WD[(c << 7) + tid];
                d0 = fmaf(wv.x, hx[c].x, d0); d1 = fmaf(wv.y, hx[c].y, d1);
                d2 = fmaf(wv.z, hx[c].z, d2); d3 = fmaf(wv.w, hx[c].w, d3);
            }
            float acc = (d0 + d1) + (d2 + d3);
            acc += __shfl_xor_sync(FULL, acc, 1);
            acc += __shfl_xor_sync(FULL, acc, 2);
            acc += __shfl_xor_sync(FULL, acc, 4);
            if (oct == 0)
                bcast_arrive(rb, (OFF_HD + rank * 16 + j) * 4u, tanha(acc + pre_r), B_D);
        }

        // ======== stage A (step t+1) hh-half part 2 — hides wait_D ========
        if (t < STEPS - 1) {
            const float4* hv = (const float4*)(h0w + cs * 64);
#pragma unroll
            for (int k = 8; k < 16; k++) {
                float4 wv = W0[((3 + k) << 7) + tid];
                float4 xq = hv[k];
                n0 = fmaf(wv.x, xq.x, n0); n1 = fmaf(wv.y, xq.y, n1);
                n2 = fmaf(wv.z, xq.z, n2); n3 = fmaf(wv.w, xq.w, n3);
            }
        }
        mbar_wait(sbase + B_D, ph);             // hD full ready

        // ======== stages E/F: redundant local (reg-resident weights) ========
        {
            const float4* xv = (const float4*)hD;
            float e0 = 0, e1 = 0, e2 = 0, e3 = 0;
#pragma unroll
            for (int k = 0; k < 32; k++) {
                e0 = fmaf(wreg[k].x, xv[k].x, e0); e1 = fmaf(wreg[k].y, xv[k].y, e1);
                e2 = fmaf(wreg[k].z, xv[k].z, e2); e3 = fmaf(wreg[k].w, xv[k].w, e3);
            }
            hidE[tid] = fmaxf(((e0 + e1) + (e2 + e3)) + bhhf[tid], 0.f);
        }
        __syncthreads();
        {
            const float4* xv = (const float4*)hidE;
            float e0 = 0, e1 = 0, e2 = 0, e3 = 0;
#pragma unroll
            for (int k = 0; k < 32; k++) {
                e0 = fmaf(wreg[k].x, xv[k].x, e0); e1 = fmaf(wreg[k].y, xv[k].y, e1);
                e2 = fmaf(wreg[k].z, xv[k].z, e2); e3 = fmaf(wreg[k].w, xv[k].w, e3);
            }
            hidF[tid] = fmaxf(((e0 + e1) + (e2 + e3)) + bhhf[tid], 0.f);
        }
        __syncthreads();
        // ======== stage G: o = sigmoid(Wh2o @ hid + b) — redundant per CTA ====
        if (tid < 96) {
            const float4* xv = (const float4*)(hidF + oct * 16);
            float e0 = 0, e1 = 0, e2 = 0, e3 = 0;
#pragma unroll
            for (int c = 0; c < 4; c++) {
                float4 wv = WO4[c * 96 + tid];
                e0 = fmaf(wv.x, xv[c].x, e0); e1 = fmaf(wv.y, xv[c].y, e1);
                e2 = fmaf(wv.z, xv[c].z, e2); e3 = fmaf(wv.w, xv[c].w, e3);
            }
            float acc = (e0 + e1) + (e2 + e3);
            acc += __shfl_xor_sync(FULL, acc, 1);
            acc += __shfl_xor_sync(FULL, acc, 2);
            acc += __shfl_xor_sync(FULL, acc, 4);
            if (oct == 0) {
                int r = tid >> 3;  // 0..11
                float ov = sigm(acc + bh2o[r]);
                obuf[r] = ov;
                if (rank == 0) dout[(size_t)t * ODIM + r] = ov;
            }
        }
        __syncthreads();

        // ======== stage A (step t+1) tail: obuf part + gates + bcast ========
        if (t < STEPS - 1) {
            float a0 = n0, a1 = n1, a2 = n2, a3 = n3;
            if (cs == 0) {
                const float4* ob4 = (const float4*)obuf;
#pragma unroll
                for (int k = 0; k < 3; k++) { float4 wv = W0[(k << 7) + tid]; FMA4(wv, ob4[k]); }
            }
            GATE_TAIL(bA, cA, OFF_H0 + q * 128 + rank * 16 + j, B_A);
        }
    }

    // ---------------- final hN / cN ----------------
    if (out_size >= STEPS * ODIM + 6 * HDIM) {
        const int fb = STEPS * ODIM;  // 49152
        if (rank == 0) {
            dout[fb + tid]       = h0b[128 + tid];  // final parity = 1
            dout[fb + 128 + tid] = h1b[128 + tid];
            dout[fb + 256 + tid] = h2b[128 + tid];
        }
        if (oct == 0) {
            dout[fb + 384 + 0 * 128 + rank * 16 + j] = cA;
            dout[fb + 384 + 1 * 128 + rank * 16 + j] = cB;
            dout[fb + 384 + 2 * 128 + rank * 16 + j] = cC;
        }
    }
}

// =====================================================================
// launch
// =====================================================================
extern "C" void kernel_launch(void* const* d_in, const int* in_sizes, int n_in,
                              void* d_out, int out_size) {
    const float* inputs = (const float*)d_in[0];
    const float* out0   = (const float*)d_in[1];
    const float* h0in   = (const float*)d_in[2];
    const float* c0in   = (const float*)d_in[3];
    const float* W_s2i  = (const float*)d_in[4];
    const float* b_s2i  = (const float*)d_in[5];
    const float* W_i2h  = (const float*)d_in[6];
    const float* b_i2h  = (const float*)d_in[7];
    const float* W_h2h  = (const float*)d_in[8];
    const float* b_h2h  = (const float*)d_in[9];
    const float* W_h2o  = (const float*)d_in[10];
    const float* b_h2o  = (const float*)d_in[11];
    const float* Wih0   = (const float*)d_in[12];
    const float* Whh0   = (const float*)d_in[13];
    const float* bih0   = (const float*)d_in[14];
    const float* bhh0   = (const float*)d_in[15];
    const float* Wih1   = (const float*)d_in[16];
    const float* Whh1   = (const float*)d_in[17];
    const float* bih1   = (const float*)d_in[18];
    const float* bhh1   = (const float*)d_in[19];
    const float* Wih2   = (const float*)d_in[20];
    const float* Whh2   = (const float*)d_in[21];
    const float* bih2   = (const float*)d_in[22];
    const float* bhh2   = (const float*)d_in[23];
    float* dout = (float*)d_out;

    cudaFuncSetAttribute(k_scan, cudaFuncAttributeMaxDynamicSharedMemorySize, SMEM_BYTES);

    k_cf<<<1, 128>>>(b_s2i, W_i2h, b_i2h);
    k_mt<<<dim3(DATA / 256, HDIM / 16), 256>>>(W_s2i, W_i2h);
    k_pre<<<STEPS / 16, 256>>>(inputs);
    k_scan<<<NCTA, TPB, SMEM_BYTES>>>(out0, h0in, c0in,
                                      W_i2h, W_h2h, b_h2h, W_h2o, b_h2o,
                                      Wih0, Whh0, bih0, bhh0,
                                      Wih1, Whh1, bih1, bhh1,
                                      Wih2, Whh2, bih2, bhh2,
                                      dout, out_size);
}

// round 15
// speedup vs baseline: 1.7689x; 1.0214x over previous
#include <cuda_runtime.h>
#include <cstdint>

// ---------------- problem constants ----------------
#define STEPS 4096
#define DATA  8192
#define EMBD  1024
#define HDIM  128
#define ODIM  12
#define NCTA  8
#define TPB   128

// ---------------- device scratch (no allocations allowed) ----------------
__device__ float g_Mt[(size_t)DATA * HDIM];     // fused weight Mt[d][i]  (4 MB)
__device__ float g_pre[(size_t)STEPS * HDIM];   // pre_i2h[t][i] + c_fused (2 MB)
__device__ float g_cf[HDIM];                    // fused bias

__device__ __forceinline__ float tanha(float x) {
    float y; asm("tanh.approx.f32 %0, %1;" : "=f"(y) : "f"(x)); return y;
}
__device__ __forceinline__ float sigm(float x) { return 0.5f + 0.5f * tanha(0.5f * x); }

#define CLUSTER_SYNC() do { \
  asm volatile("barrier.cluster.arrive.aligned;" ::: "memory"); \
  asm volatile("barrier.cluster.wait.aligned;"   ::: "memory"); } while (0)

// NOTE: parameter names must not collide with float4 member tokens x/y/z/w
#define FMA4(W_, X_) do { a0 = fmaf((W_).x,(X_).x,a0); a1 = fmaf((W_).y,(X_).y,a1); \
                          a2 = fmaf((W_).z,(X_).z,a2); a3 = fmaf((W_).w,(X_).w,a3); } while (0)

// =====================================================================
// K0: c_fused[i] = b_i2h[i] + sum_e b_s2i[e] * W_i2h[i][e]
// =====================================================================
__global__ void k_cf(const float* __restrict__ b_s2i,
                     const float* __restrict__ Wi2h,
                     const float* __restrict__ b_i2h) {
    int i = threadIdx.x;  // 128 threads
    const float4* b4 = (const float4*)b_s2i;
    const float4* w4 = (const float4*)(Wi2h + (size_t)i * 1152);
    float a0 = 0, a1 = 0, a2 = 0, a3 = 0;
    for (int k = 0; k < EMBD / 4; k++) { float4 bv = b4[k], wv = w4[k]; FMA4(wv, bv); }
    g_cf[i] = b_i2h[i] + ((a0 + a1) + (a2 + a3));
}

// =====================================================================
// K1: Mt[d][i] = sum_e Ws2i[e][d] * Wi2h[i][e]     grid(32,8), 256 thr
// =====================================================================
__global__ void __launch_bounds__(256) k_mt(const float* __restrict__ Ws2i,
                                            const float* __restrict__ Wi2h) {
    __shared__ float we[16][128];
    int d  = blockIdx.x * 256 + threadIdx.x;
    int i0 = blockIdx.y * 16;
    float acc[16];
#pragma unroll
    for (int ii = 0; ii < 16; ii++) acc[ii] = 0.f;
    for (int e0 = 0; e0 < EMBD; e0 += 128) {
#pragma unroll
        for (int k = 0; k < 8; k++) {
            int idx = k * 256 + threadIdx.x;
            int ii = idx >> 7, ee = idx & 127;
            we[ii][ee] = Wi2h[(size_t)(i0 + ii) * 1152 + e0 + ee];
        }
        __syncthreads();
        for (int ee = 0; ee < 128; ee++) {
            float ws = Ws2i[(size_t)(e0 + ee) * DATA + d];
#pragma unroll
            for (int ii = 0; ii < 16; ii++) acc[ii] = fmaf(we[ii][ee], ws, acc[ii]);
        }
        __syncthreads();
    }
#pragma unroll
    for (int ii = 0; ii < 16; ii++) g_Mt[(size_t)d * HDIM + i0 + ii] = acc[ii];
}

// =====================================================================
// K2: pre[t][i] = c_fused[i] + sum_d inputs[t][d] * Mt[d][i]
// =====================================================================
__global__ void __launch_bounds__(256) k_pre(const float* __restrict__ inputs) {
    __shared__ float xin[16 * 64];
    __shared__ float wm[64 * 128];
    int t0   = blockIdx.x * 16;
    int i    = threadIdx.x & 127;
    int trow = threadIdx.x >> 7;  // 0..1
    float acc[8];
#pragma unroll
    for (int k = 0; k < 8; k++) acc[k] = 0.f;
    for (int d0 = 0; d0 < DATA; d0 += 64) {
        {
            int idx = threadIdx.x * 4;
            int tt = idx >> 6, dd = idx & 63;
            *(float4*)&xin[idx] = *(const float4*)&inputs[(size_t)(t0 + tt) * DATA + d0 + dd];
        }
#pragma unroll
        for (int k = 0; k < 8; k++) {
            int x4 = (k * 256 + threadIdx.x) * 4;
            *(float4*)&wm[x4] = *(const float4*)&g_Mt[(size_t)d0 * HDIM + x4];
        }
        __syncthreads();
        for (int dd = 0; dd < 64; dd++) {
            float m = wm[dd * 128 + i];
#pragma unroll
            for (int tt = 0; tt < 8; tt++)
                acc[tt] = fmaf(xin[(trow + tt * 2) * 64 + dd], m, acc[tt]);
        }
        __syncthreads();
    }
    float cf = g_cf[i];
#pragma unroll
    for (int tt = 0; tt < 8; tt++)
        g_pre[(size_t)(t0 + trow + tt * 2) * HDIM + i] = acc[tt] + cf;
}

// =====================================================================
// K3: the sequential scan — 8-CTA cluster, 128 thr/CTA, mbarrier p2p sync
//  R14: lane-distributed broadcasts (lane oct -> CTA oct), redundant c per
//  j-group, bias added post-reduction (one fewer serial shuffle).
// =====================================================================
#define OFF_L0W   0         /* 9728  */
#define OFF_L1W   9728      /* 16384 */
#define OFF_L2W   26112     /* 16384 */
#define OFF_WD    42496     /* 2048  */
#define OFF_BHH   44544     /* 128   */
#define OFF_BH2O  44672     /* 16    */
#define OFF_H0    44688     /* 256   */
#define OFF_H1    44944     /* 256   */
#define OFF_H2    45200     /* 256   */
#define OFF_HD    45456     /* 128   */
#define OFF_HE    45584     /* 128   */
#define OFF_HF    45712     /* 128   */
#define OFF_OBUF  45840     /* 16    */
#define OFF_WO    45856     /* 1536  */
#define OFF_MBAR  47392     /* 4 mbarriers = 8 floats (8B aligned) */
#define SMEM_FLOATS 47400
#define SMEM_BYTES  (SMEM_FLOATS * 4)

// barrier byte offsets (from smem base)
#define B_A ((OFF_MBAR + 0) * 4)
#define B_B ((OFF_MBAR + 2) * 4)
#define B_C ((OFF_MBAR + 4) * 4)
#define B_D ((OFF_MBAR + 6) * 4)

__device__ __forceinline__ void mbar_wait(uint32_t mbar, uint32_t ph) {
    asm volatile(
        "{\n\t"
        ".reg .pred P;\n\t"
        "WL_%=:\n\t"
        "mbarrier.try_wait.parity.acquire.cluster.shared::cta.b64 P, [%0], %1, 0x989680;\n\t"
        "@P bra.uni WD_%=;\n\t"
        "bra.uni WL_%=;\n\t"
        "WD_%=:\n\t"
        "}"
        :: "r"(mbar), "r"(ph) : "memory");
}

// single-lane remote store + arrive (release orders store before arrive)
__device__ __forceinline__ void send_one(uint32_t rbk, uint32_t doff, float v,
                                         uint32_t boff) {
    uint32_t vb = __float_as_uint(v);
    asm volatile("st.shared::cluster.u32 [%0], %1;" :: "r"(rbk + doff), "r"(vb) : "memory");
    asm volatile("mbarrier.arrive.shared::cluster.b64 _, [%0];" :: "r"(rbk + boff) : "memory");
}

__global__ void __launch_bounds__(TPB, 1) __cluster_dims__(NCTA, 1, 1)
k_scan(const float* __restrict__ out0, const float* __restrict__ h0in,
       const float* __restrict__ c0in,
       const float* __restrict__ Wi2h, const float* __restrict__ Wh2h,
       const float* __restrict__ bh2h_g,
       const float* __restrict__ Wh2o, const float* __restrict__ bh2o_g,
       const float* __restrict__ Wih0, const float* __restrict__ Whh0,
       const float* __restrict__ bih0, const float* __restrict__ bhh0,
       const float* __restrict__ Wih1, const float* __restrict__ Whh1,
       const float* __restrict__ bih1, const float* __restrict__ bhh1,
       const float* __restrict__ Wih2, const float* __restrict__ Whh2,
       const float* __restrict__ bih2, const float* __restrict__ bhh2,
       float* __restrict__ dout, int out_size) {
    extern __shared__ float sm[];
    const int tid  = threadIdx.x;
    const int rank = blockIdx.x;
    const unsigned FULL = 0xffffffffu;
    const uint32_t sbase = (uint32_t)__cvta_generic_to_shared(sm);

    float* l0w   = sm + OFF_L0W;
    float* l1w   = sm + OFF_L1W;
    float* l2w   = sm + OFF_L2W;
    float* wd    = sm + OFF_WD;
    float* bhhf  = sm + OFF_BHH;
    float* bh2o  = sm + OFF_BH2O;
    float* h0b   = sm + OFF_H0;
    float* h1b   = sm + OFF_H1;
    float* h2b   = sm + OFF_H2;
    float* hD    = sm + OFF_HD;
    float* hidE  = sm + OFF_HE;
    float* hidF  = sm + OFF_HF;
    float* obuf  = sm + OFF_OBUF;
    float* wo    = sm + OFF_WO;

    const int j    = tid >> 3;
    const int g    = (tid >> 1) & 3;
    const int cs   = tid & 1;
    const int oct  = tid & 7;
    const int lane = tid & 31;
    const int base = lane & ~7;

    // remote smem base of every cluster CTA (mapa hoisted out of the loop)
    uint32_t rb[NCTA];
#pragma unroll
    for (int rk = 0; rk < NCTA; rk++)
        asm("mapa.shared::cluster.u32 %0, %1, %2;" : "=r"(rb[rk]) : "r"(sbase), "r"(rk));
    const uint32_t rbme = rb[oct];   // this lane's target CTA

    // mbarrier init (count = 16 j-groups * 8 source CTAs = 128)
    if (tid == 0) {
#pragma unroll
        for (int b = 0; b < 4; b++)
            asm volatile("mbarrier.init.shared.b64 [%0], %1;"
                         :: "r"(sbase + B_A + 8u * b), "r"(128) : "memory");
    }

    // ---------------- load LSTM weight slices ----------------
    for (int idx = tid; idx < 16384; idx += TPB) {
        int s = idx >> 9, rem = idx & 511;
        int t = rem >> 2, c = rem & 3;
        int p = s >> 4, k = s & 15;
        int jj = t >> 3, gg = (t >> 1) & 3, cc = t & 1;
        int R = gg * 128 + rank * 16 + jj;
        int col = cc * 64 + k * 4 + c;
        l1w[idx] = p ? Whh1[(size_t)R * 128 + col] : Wih1[(size_t)R * 128 + col];
        l2w[idx] = p ? Whh2[(size_t)R * 128 + col] : Wih2[(size_t)R * 128 + col];
    }
    for (int idx = tid; idx < 9728; idx += TPB) {
        int s = idx >> 9, rem = idx & 511;
        int t = rem >> 2, c = rem & 3;
        int jj = t >> 3, gg = (t >> 1) & 3, cc = t & 1;
        int R = gg * 128 + rank * 16 + jj;
        float v;
        if (s < 3) v = (cc == 0) ? Wih0[(size_t)R * 12 + s * 4 + c] : 0.f;
        else       v = Whh0[(size_t)R * 128 + cc * 64 + (s - 3) * 4 + c];
        l0w[idx] = v;
    }
    for (int idx = tid; idx < 2048; idx += TPB) {
        int c = idx >> 9, rem = idx & 511, t = rem >> 2, e = rem & 3;
        int r = t >> 3, oc = t & 7;
        wd[idx] = Wi2h[(size_t)(rank * 16 + r) * 1152 + 1024 + oc * 16 + c * 4 + e];
    }
    // G-stage weights in interleaved SMEM (96 active lanes, conflict-free)
    for (int idx = tid; idx < 1536; idx += TPB) {
        int c = idx / 384, rem = idx % 384;
        int t = rem >> 2, e = rem & 3;
        int r = t >> 3, oc = t & 7;
        wo[idx] = Wh2o[(size_t)r * 128 + oc * 16 + c * 4 + e];
    }
    bhhf[tid] = bh2h_g[tid];
    if (tid < 12) { bh2o[tid] = bh2o_g[tid]; obuf[tid] = out0[tid]; }
    if (tid >= 12 && tid < 16) obuf[tid] = 0.f;
    h0b[128 + tid] = h0in[tid];
    h1b[128 + tid] = h0in[128 + tid];
    h2b[128 + tid] = h0in[256 + tid];

    // biases in ALL lanes (added post-reduction)
    float bA, bB, bC;
    {
        int R = g * 128 + rank * 16 + j;
        bA = bih0[R] + bhh0[R];
        bB = bih1[R] + bhh1[R];
        bC = bih2[R] + bhh2[R];
    }
    // cell state redundantly maintained by ALL 8 lanes of each j-group
    float cA = c0in[0 * 128 + rank * 16 + j];
    float cB = c0in[1 * 128 + rank * 16 + j];
    float cC = c0in[2 * 128 + rank * 16 + j];

    // E/F weights permanently in registers
    float4 wreg[32];
#pragma unroll
    for (int k = 0; k < 32; k++)
        wreg[k] = *(const float4*)&Wh2h[(size_t)tid * 128 + k * 4];

    __syncthreads();
    CLUSTER_SYNC();   // all SMEM init + mbarrier init visible cluster-wide

    const float4* W0 = (const float4*)l0w;
    const float4* W1 = (const float4*)l1w;
    const float4* W2 = (const float4*)l2w;
    const float4* WD = (const float4*)wd;
    const float4* WO4 = (const float4*)wo;

    // gate tail: pair-combine, bias post-reduction in both lanes, parallel
    // per-gate activation, parallel gather, redundant c update in all lanes,
    // lane `oct` sends h to CTA `oct` only.
    #define GATE_TAIL(BIAS, CREG, DOFF, BOFF) do {                              \
        float acc = (a0 + a1) + (a2 + a3);                                      \
        acc += __shfl_xor_sync(FULL, acc, 1);                                   \
        acc += (BIAS);                                                          \
        float xs = (g == 2) ? acc : 0.5f * acc;                                 \
        float tv = tanha(xs);                                                   \
        float act = (g == 2) ? tv : fmaf(0.5f, tv, 0.5f);                       \
        float iac = __shfl_sync(FULL, act, base + 0);                           \
        float fac = __shfl_sync(FULL, act, base + 2);                           \
        float gac = __shfl_sync(FULL, act, base + 4);                           \
        float oac = __shfl_sync(FULL, act, base + 6);                           \
        CREG = fmaf(fac, CREG, iac * gac);                                      \
        float hv = oac * tanha(CREG);                                           \
        send_one(rbme, (DOFF) * 4u, hv, BOFF);                                  \
    } while (0)

    // ---------------- prologue: stage A of step 0 ----------------
    {
        const float4* hv = (const float4*)(h0b + 128 + cs * 64);  // parity 1 init
        float a0 = 0, a1 = 0, a2 = 0, a3 = 0;
#pragma unroll
        for (int k = 0; k < 16; k++) { float4 wv = W0[((3 + k) << 7) + tid]; FMA4(wv, hv[k]); }
        if (cs == 0) {
            const float4* ob4 = (const float4*)obuf;
#pragma unroll
            for (int k = 0; k < 3; k++) { float4 wv = W0[(k << 7) + tid]; FMA4(wv, ob4[k]); }
        }
        GATE_TAIL(bA, cA, OFF_H0 + 0 + rank * 16 + j, B_A);
    }

    // ---------------- main scan ----------------
#pragma unroll 1
    for (int t = 0; t < STEPS; t++) {
        const int p = t & 1, q = p ^ 1;
        const uint32_t ph = (uint32_t)(t & 1);
        float* h0w = h0b + p * 128;
        float* h1w = h1b + p * 128; const float* h1r = h1b + q * 128;
        float* h2w = h2b + p * 128; const float* h2r = h2b + q * 128;

        float pre_r = g_pre[(size_t)t * HDIM + rank * 16 + j];

        // ======== stage B: LSTM layer 1 — hh half hoisted over wait_A ========
        float a0 = 0, a1 = 0, a2 = 0, a3 = 0;
        {
            const float4* pv = (const float4*)(h1r + cs * 64);
#pragma unroll
            for (int k = 0; k < 16; k++) { float4 wv = W1[((16 + k) << 7) + tid]; FMA4(wv, pv[k]); }
        }
        mbar_wait(sbase + B_A, ph);             // h0(t) ready everywhere
        {
            const float4* xv = (const float4*)(h0w + cs * 64);
#pragma unroll
            for (int k = 0; k < 16; k++) { float4 wv = W1[(k << 7) + tid]; FMA4(wv, xv[k]); }
        }
        GATE_TAIL(bB, cB, OFF_H1 + p * 128 + rank * 16 + j, B_B);

        // ======== stage C: LSTM layer 2 — hh half hoisted over wait_B ========
        a0 = 0; a1 = 0; a2 = 0; a3 = 0;
        {
            const float4* pv = (const float4*)(h2r + cs * 64);
#pragma unroll
            for (int k = 0; k < 16; k++) { float4 wv = W2[((16 + k) << 7) + tid]; FMA4(wv, pv[k]); }
        }
        mbar_wait(sbase + B_B, ph);             // h1(t) ready
        {
            const float4* xv = (const float4*)(h1w + cs * 64);
#pragma unroll
            for (int k = 0; k < 16; k++) { float4 wv = W2[(k << 7) + tid]; FMA4(wv, xv[k]); }
        }
        GATE_TAIL(bC, cC, OFF_H2 + p * 128 + rank * 16 + j, B_C);

        // ======== stage A (step t+1) hh-half part 1 — hides wait_C ========
        float n0 = 0, n1 = 0, n2 = 0, n3 = 0;
        if (t < STEPS - 1) {
            const float4* hv = (const float4*)(h0w + cs * 64);  // h0(t), acquired
#pragma unroll
            for (int k = 0; k < 8; k++) {
                float4 wv = W0[((3 + k) << 7) + tid];
                float4 xq = hv[k];
                n0 = fmaf(wv.x, xq.x, n0); n1 = fmaf(wv.y, xq.y, n1);
                n2 = fmaf(wv.z, xq.z, n2); n3 = fmaf(wv.w, xq.w, n3);
            }
        }
        mbar_wait(sbase + B_C, ph);             // h2(t) ready

        // ======== stage D: hid = tanh(pre + Wi2h_h @ h2) — distributed ========
        {
            const float4* hx = (const float4*)(h2w + oct * 16);
            float d0 = 0, d1 = 0, d2 = 0, d3 = 0;
#pragma unroll
            for (int c = 0; c < 4; c++) {
                float4 wv = WD[(c << 7) + tid];
                d0 = fmaf(wv.x, hx[c].x, d0); d1 = fmaf(wv.y, hx[c].y, d1);
                d2 = fmaf(wv.z, hx[c].z, d2); d3 = fmaf(wv.w, hx[c].w, d3);
            }
            float acc = (d0 + d1) + (d2 + d3);
            acc += __shfl_xor_sync(FULL, acc, 1);
            acc += __shfl_xor_sync(FULL, acc, 2);
            acc += __shfl_xor_sync(FULL, acc, 4);
            float hv = tanha(acc + pre_r);      // identical in all 8 lanes
            send_one(rbme, (OFF_HD + rank * 16 + j) * 4u, hv, B_D);
        }

        // ======== stage A (step t+1) hh-half part 2 — hides wait_D ========
        if (t < STEPS - 1) {
            const float4* hv = (const float4*)(h0w + cs * 64);
#pragma unroll
            for (int k = 8; k < 16; k++) {
                float4 wv = W0[((3 + k) << 7) + tid];
                float4 xq = hv[k];
                n0 = fmaf(wv.x, xq.x, n0); n1 = fmaf(wv.y, xq.y, n1);
                n2 = fmaf(wv.z, xq.z, n2); n3 = fmaf(wv.w, xq.w, n3);
            }
        }
        mbar_wait(sbase + B_D, ph);             // hD full ready

        // ======== stages E/F: redundant local (reg-resident weights) ========
        {
            const float4* xv = (const float4*)hD;
            float e0 = 0, e1 = 0, e2 = 0, e3 = 0;
#pragma unroll
            for (int k = 0; k < 32; k++) {
                e0 = fmaf(wreg[k].x, xv[k].x, e0); e1 = fmaf(wreg[k].y, xv[k].y, e1);
                e2 = fmaf(wreg[k].z, xv[k].z, e2); e3 = fmaf(wreg[k].w, xv[k].w, e3);
            }
            hidE[tid] = fmaxf(((e0 + e1) + (e2 + e3)) + bhhf[tid], 0.f);
        }
        __syncthreads();
        {
            const float4* xv = (const float4*)hidE;
            float e0 = 0, e1 = 0, e2 = 0, e3 = 0;
#pragma unroll
            for (int k = 0; k < 32; k++) {
                e0 = fmaf(wreg[k].x, xv[k].x, e0); e1 = fmaf(wreg[k].y, xv[k].y, e1);
                e2 = fmaf(wreg[k].z, xv[k].z, e2); e3 = fmaf(wreg[k].w, xv[k].w, e3);
            }
            hidF[tid] = fmaxf(((e0 + e1) + (e2 + e3)) + bhhf[tid], 0.f);
        }
        __syncthreads();
        // ======== stage G: o = sigmoid(Wh2o @ hid + b) — redundant per CTA ====
        if (tid < 96) {
            const float4* xv = (const float4*)(hidF + oct * 16);
            float e0 = 0, e1 = 0, e2 = 0, e3 = 0;
#pragma unroll
            for (int c = 0; c < 4; c++) {
                float4 wv = WO4[c * 96 + tid];
                e0 = fmaf(wv.x, xv[c].x, e0); e1 = fmaf(wv.y, xv[c].y, e1);
                e2 = fmaf(wv.z, xv[c].z, e2); e3 = fmaf(wv.w, xv[c].w, e3);
            }
            float acc = (e0 + e1) + (e2 + e3);
            acc += __shfl_xor_sync(FULL, acc, 1);
            acc += __shfl_xor_sync(FULL, acc, 2);
            acc += __shfl_xor_sync(FULL, acc, 4);
            if (oct == 0) {
                int r = tid >> 3;  // 0..11
                float ov = sigm(acc + bh2o[r]);
                obuf[r] = ov;
                if (rank == 0) dout[(size_t)t * ODIM + r] = ov;
            }
        }
        __syncthreads();

        // ======== stage A (step t+1) tail: obuf part + gates + bcast ========
        if (t < STEPS - 1) {
            float a0 = n0, a1 = n1, a2 = n2, a3 = n3;
            if (cs == 0) {
                const float4* ob4 = (const float4*)obuf;
#pragma unroll
                for (int k = 0; k < 3; k++) { float4 wv = W0[(k << 7) + tid]; FMA4(wv, ob4[k]); }
            }
            GATE_TAIL(bA, cA, OFF_H0 + q * 128 + rank * 16 + j, B_A);
        }
    }

    // ---------------- final hN / cN ----------------
    if (out_size >= STEPS * ODIM + 6 * HDIM) {
        const int fb = STEPS * ODIM;  // 49152
        if (rank == 0) {
            dout[fb + tid]       = h0b[128 + tid];  // final parity = 1
            dout[fb + 128 + tid] = h1b[128 + tid];
            dout[fb + 256 + tid] = h2b[128 + tid];
        }
        if (oct == 0) {
            dout[fb + 384 + 0 * 128 + rank * 16 + j] = cA;
            dout[fb + 384 + 1 * 128 + rank * 16 + j] = cB;
            dout[fb + 384 + 2 * 128 + rank * 16 + j] = cC;
        }
    }
}

// =====================================================================
// launch
// =====================================================================
extern "C" void kernel_launch(void* const* d_in, const int* in_sizes, int n_in,
                              void* d_out, int out_size) {
    const float* inputs = (const float*)d_in[0];
    const float* out0   = (const float*)d_in[1];
    const float* h0in   = (const float*)d_in[2];
    const float* c0in   = (const float*)d_in[3];
    const float* W_s2i  = (const float*)d_in[4];
    const float* b_s2i  = (const float*)d_in[5];
    const float* W_i2h  = (const float*)d_in[6];
    const float* b_i2h  = (const float*)d_in[7];
    const float* W_h2h  = (const float*)d_in[8];
    const float* b_h2h  = (const float*)d_in[9];
    const float* W_h2o  = (const float*)d_in[10];
    const float* b_h2o  = (const float*)d_in[11];
    const float* Wih0   = (const float*)d_in[12];
    const float* Whh0   = (const float*)d_in[13];
    const float* bih0   = (const float*)d_in[14];
    const float* bhh0   = (const float*)d_in[15];
    const float* Wih1   = (const float*)d_in[16];
    const float* Whh1   = (const float*)d_in[17];
    const float* bih1   = (const float*)d_in[18];
    const float* bhh1   = (const float*)d_in[19];
    const float* Wih2   = (const float*)d_in[20];
    const float* Whh2   = (const float*)d_in[21];
    const float* bih2   = (const float*)d_in[22];
    const float* bhh2   = (const float*)d_in[23];
    float* dout = (float*)d_out;

    cudaFuncSetAttribute(k_scan, cudaFuncAttributeMaxDynamicSharedMemorySize, SMEM_BYTES);

    k_cf<<<1, 128>>>(b_s2i, W_i2h, b_i2h);
    k_mt<<<dim3(DATA / 256, HDIM / 16), 256>>>(W_s2i, W_i2h);
    k_pre<<<STEPS / 16, 256>>>(inputs);
    k_scan<<<NCTA, TPB, SMEM_BYTES>>>(out0, h0in, c0in,
                                      W_i2h, W_h2h, b_h2h, W_h2o, b_h2o,
                                      Wih0, Whh0, bih0, bhh0,
                                      Wih1, Whh1, bih1, bhh1,
                                      Wih2, Whh2, bih2, bhh2,
                                      dout, out_size);
}